// round 3
// baseline (speedup 1.0000x reference)
#include <cuda_runtime.h>
#include <math.h>

#define KSZ 3
#define C_IN 64
#define CE 576          // 64*9
#define HD 128
#define WD 128
#define BD 8
#define OUP 128
#define EPSV 1e-5f
#define TP 16           // pixels per tile (along w)

// ---------------- device scratch (no allocations allowed) ----------------
__device__ float  g_genW[CE * 9];     // BN-fused depthwise weights
__device__ float  g_genH[CE];         // BN-fused depthwise shift
__device__ float  g_convS[OUP];       // final BN scale
__device__ float  g_convH[OUP];       // final BN shift
__device__ float4 g_stats[BD * C_IN]; // per (b,c): {A, alpha, beta, 1-wa}

// ---------------- helpers ----------------
__device__ __forceinline__ void fma2(unsigned long long& d, unsigned long long a,
                                     unsigned long long b) {
    asm("fma.rn.f32x2 %0, %1, %2, %0;" : "+l"(d) : "l"(a), "l"(b));
}
__device__ __forceinline__ unsigned long long dup2(float v) {
    unsigned long long r;
    asm("mov.b64 %0, {%1, %1};" : "=l"(r) : "f"(v));
    return r;
}
__device__ __forceinline__ void unpk(unsigned long long v, float& lo, float& hi) {
    asm("mov.b64 {%0, %1}, %2;" : "=f"(lo), "=f"(hi) : "l"(v));
}
__device__ __forceinline__ float sigm(float x) {
    return 1.0f / (1.0f + __expf(-x));
}

// ---------------- kernel 0: fuse BN params ----------------
__global__ void prep_kernel(const float* __restrict__ gen_w,
                            const float* __restrict__ gg, const float* __restrict__ gb,
                            const float* __restrict__ gm, const float* __restrict__ gv,
                            const float* __restrict__ cg, const float* __restrict__ cb,
                            const float* __restrict__ cm, const float* __restrict__ cv) {
    int i = blockIdx.x * blockDim.x + threadIdx.x;
    if (i < CE) {
        float s = gg[i] * rsqrtf(gv[i] + EPSV);
        g_genH[i] = gb[i] - gm[i] * s;
#pragma unroll
        for (int j = 0; j < 9; j++) g_genW[i * 9 + j] = s * gen_w[i * 9 + j];
    }
    if (i < OUP) {
        float s = cg[i] * rsqrtf(cv[i] + EPSV);
        g_convS[i] = s;
        g_convH[i] = cb[i] - cm[i] * s;
    }
}

// ---------------- kernel 1: per-(b,c) statistics ----------------
// One block per (b,c). Recomputes v = relu(bn(dwconv)) for all 9*H*W values,
// reduces sum / sumsq, then folds gates into {A, alpha, beta}.
__global__ __launch_bounds__(256) void stats_kernel(
    const float* __restrict__ x,
    const float* __restrict__ gn_w, const float* __restrict__ gn_b,
    const float* __restrict__ cweight, const float* __restrict__ cbias,
    const float* __restrict__ sweight, const float* __restrict__ sbias,
    const float* __restrict__ wa_p) {
    __shared__ float sW[81];
    __shared__ float sH[9];
    __shared__ float redS[8], redQ[8];

    int bc = blockIdx.x;
    int b = bc >> 6, c = bc & 63;
    int tid = threadIdx.x;

    if (tid < 81) sW[tid] = g_genW[c * 81 + tid];
    if (tid < 9) sH[tid] = g_genH[c * 9 + tid];
    __syncthreads();

    const float* xc = x + (size_t)(b * C_IN + c) * HD * WD;
    float sum = 0.f, ss = 0.f;

    for (int i = tid; i < HD * WD; i += 256) {
        int h = i >> 7, w = i & 127;
        float xn[9];
#pragma unroll
        for (int dh = 0; dh < 3; dh++) {
            int hh = h + dh - 1;
            bool hv = (hh >= 0) && (hh < HD);
#pragma unroll
            for (int dw = 0; dw < 3; dw++) {
                int ww = w + dw - 1;
                xn[dh * 3 + dw] =
                    (hv && ww >= 0 && ww < WD) ? xc[hh * WD + ww] : 0.f;
            }
        }
#pragma unroll
        for (int t = 0; t < 9; t++) {
            float a = sH[t];
#pragma unroll
            for (int j = 0; j < 9; j++) a = fmaf(sW[t * 9 + j], xn[j], a);
            float v = fmaxf(a, 0.f);
            sum += v;
            ss = fmaf(v, v, ss);
        }
    }
#pragma unroll
    for (int o = 16; o; o >>= 1) {
        sum += __shfl_down_sync(0xffffffffu, sum, o);
        ss += __shfl_down_sync(0xffffffffu, ss, o);
    }
    if ((tid & 31) == 0) { redS[tid >> 5] = sum; redQ[tid >> 5] = ss; }
    __syncthreads();
    if (tid == 0) {
        float S = 0.f, Q = 0.f;
#pragma unroll
        for (int i = 0; i < 8; i++) { S += redS[i]; Q += redQ[i]; }
        const float N = 9.0f * HD * WD;
        float mean = S / N;
        float var = Q / N - mean * mean;
        int cg = c & 7;
        float wa = *wa_p;
        float A = wa * sigm(fmaf(cweight[cg], mean, cbias[cg]));
        float inv = rsqrtf(var + EPSV);
        float alpha = sweight[cg] * gn_w[cg] * inv;
        float beta = fmaf(sweight[cg], gn_b[cg] - mean * inv * gn_w[cg], sbias[cg]);
        g_stats[bc] = make_float4(A, alpha, beta, 1.0f - wa);
    }
}

// ---------------- kernel 2: fused main ----------------
// Block: 256 threads, tile = 16 pixels (one row segment) x all 128 out-channels.
// Stage 1: u[p][k] = f(v), k = c*9+t. Stage 2: z = u @ conv_w^T via f32x2 FMA.
// Shared (floats): us[16][578] | ws[64][132] | sst[64]f4  (~71.8 KB -> 3 CTAs/SM)
#define US_STRIDE 578
#define WS_STRIDE 132
#define SMEM_FLOATS (TP * US_STRIDE + 64 * WS_STRIDE + 64 * 4)

__global__ __launch_bounds__(256) void main_kernel(
    const float* __restrict__ x, const float* __restrict__ conv_w,
    float* __restrict__ out) {
    extern __shared__ float sm[];
    float* us = sm;                         // [TP][578]
    float* ws = us + TP * US_STRIDE;        // [64][132]
    float4* sst = (float4*)(ws + 64 * WS_STRIDE);  // [64]

    int tid = threadIdx.x;
    int b = blockIdx.z, h = blockIdx.y, w0 = blockIdx.x * TP;

    if (tid < 64) sst[tid] = g_stats[b * 64 + tid];
    __syncthreads();

    // ---- stage 1: compute u for 16 pixels x 64 channels (1024 items) ----
#pragma unroll
    for (int it = 0; it < 4; it++) {
        int item = it * 256 + tid;
        int p = item & 15, c = item >> 4;
        int wq = w0 + p;
        const float* xc = x + ((size_t)(b * C_IN + c) * HD + h) * WD;
        float xn[9];
#pragma unroll
        for (int dh = 0; dh < 3; dh++) {
            int hh = h + dh - 1;
            bool hv = (hh >= 0) && (hh < HD);
#pragma unroll
            for (int dw = 0; dw < 3; dw++) {
                int ww = wq + dw - 1;
                xn[dh * 3 + dw] =
                    (hv && ww >= 0 && ww < WD) ? xc[(dh - 1) * WD + ww] : 0.f;
            }
        }
        float4 st = sst[c];
        float* up = us + p * US_STRIDE + c * 9;
        const float* wc = g_genW + c * 81;   // L1-resident, broadcast per 16 threads
        const float* hc = g_genH + c * 9;
#pragma unroll
        for (int t = 0; t < 9; t++) {
            float a = hc[t];
#pragma unroll
            for (int j = 0; j < 9; j++) a = fmaf(wc[t * 9 + j], xn[j], a);
            float v = fmaxf(a, 0.f);
            float sg = sigm(fmaf(st.y, v, st.z));
            up[t] = v * fmaf(st.w, sg, st.x);
        }
    }

    // ---- stage 2: GEMM [16 x 576] . [576 x 128] ----
    int p = tid & 15;
    int o8 = (tid >> 4) * 8;
    unsigned long long acc[4] = {0ull, 0ull, 0ull, 0ull};  // (0.f,0.f) pairs

    for (int cc = 0; cc < 9; cc++) {
        __syncthreads();
        // load 64-wide k-chunk of conv_w transposed into ws[kk][o]
        for (int idx = tid; idx < 64 * 128; idx += 256) {
            int o = idx >> 6, kk = idx & 63;
            ws[kk * WS_STRIDE + o] = conv_w[o * CE + cc * 64 + kk];
        }
        __syncthreads();
        const float* urow = us + p * US_STRIDE + cc * 64;
#pragma unroll 8
        for (int kk = 0; kk < 64; kk++) {
            unsigned long long u2 = dup2(urow[kk]);
            const longlong2* wv =
                (const longlong2*)(ws + kk * WS_STRIDE + o8);
            longlong2 wA = wv[0];
            longlong2 wB = wv[1];
            fma2(acc[0], (unsigned long long)wA.x, u2);
            fma2(acc[1], (unsigned long long)wA.y, u2);
            fma2(acc[2], (unsigned long long)wB.x, u2);
            fma2(acc[3], (unsigned long long)wB.y, u2);
        }
    }

    // ---- epilogue: BN + SiLU, coalesced stores ----
    size_t obase = ((size_t)b * OUP * HD + h) * WD + w0 + p;
#pragma unroll
    for (int q = 0; q < 4; q++) {
        float lo, hi;
        unpk(acc[q], lo, hi);
        int o0 = o8 + 2 * q, o1 = o0 + 1;
        float z0 = fmaf(lo, g_convS[o0], g_convH[o0]);
        float z1 = fmaf(hi, g_convS[o1], g_convH[o1]);
        out[obase + (size_t)o0 * (HD * WD)] = z0 * sigm(z0);
        out[obase + (size_t)o1 * (HD * WD)] = z1 * sigm(z1);
    }
}

// ---------------- launch ----------------
extern "C" void kernel_launch(void* const* d_in, const int* in_sizes, int n_in,
                              void* d_out, int out_size) {
    const float* x        = (const float*)d_in[0];
    const float* gen_w    = (const float*)d_in[1];
    const float* gen_bn_g = (const float*)d_in[2];
    const float* gen_bn_b = (const float*)d_in[3];
    const float* gen_bn_m = (const float*)d_in[4];
    const float* gen_bn_v = (const float*)d_in[5];
    const float* gn_w     = (const float*)d_in[6];
    const float* gn_b     = (const float*)d_in[7];
    const float* cweight  = (const float*)d_in[8];
    const float* cbias    = (const float*)d_in[9];
    const float* sweight  = (const float*)d_in[10];
    const float* sbias    = (const float*)d_in[11];
    const float* wa       = (const float*)d_in[12];
    const float* conv_w   = (const float*)d_in[13];
    const float* cbn_g    = (const float*)d_in[14];
    const float* cbn_b    = (const float*)d_in[15];
    const float* cbn_m    = (const float*)d_in[16];
    const float* cbn_v    = (const float*)d_in[17];
    float* out = (float*)d_out;

    prep_kernel<<<3, 256>>>(gen_w, gen_bn_g, gen_bn_b, gen_bn_m, gen_bn_v,
                            cbn_g, cbn_b, cbn_m, cbn_v);
    stats_kernel<<<BD * C_IN, 256>>>(x, gn_w, gn_b, cweight, cbias, sweight,
                                     sbias, wa);

    int smem_bytes = SMEM_FLOATS * (int)sizeof(float);
    cudaFuncSetAttribute(main_kernel, cudaFuncAttributeMaxDynamicSharedMemorySize,
                         smem_bytes);
    dim3 grid(WD / TP, HD, BD);
    main_kernel<<<grid, 256, smem_bytes>>>(x, conv_w, out);
}